// round 2
// baseline (speedup 1.0000x reference)
#include <cuda_runtime.h>
#include <math.h>

#define T 8192
#define H 2048
#define IN 4096
#define E 8

#define BM 64
#define BN 64
#define BK 16

// ---- scratch (device globals; no runtime allocation) ----
__device__ int   g_counts[E];
__device__ int   g_offsets[E];
__device__ int   g_lists[E][T];
__device__ float g_coefs[E][T];
__device__ float g_h[(size_t)2 * T * IN];   // 16384 x 4096 fp32 = 256 MB

// ---------------------------------------------------------
__global__ void zero_counts_kernel() {
    if (threadIdx.x < E) g_counts[threadIdx.x] = 0;
}

// One warp per token: logits over 8 experts, softmax, top-2, append to lists.
__global__ void router_kernel(const float* __restrict__ x,
                              const float* __restrict__ gw) {
    int warps_per_blk = blockDim.x >> 5;
    int t = blockIdx.x * warps_per_blk + (threadIdx.x >> 5);
    int lane = threadIdx.x & 31;
    if (t >= T) return;

    float acc[E];
#pragma unroll
    for (int e = 0; e < E; e++) acc[e] = 0.f;

    const float* xr = x + (size_t)t * H;
    for (int c = lane * 4; c < H; c += 32 * 4) {
        float4 xv = *(const float4*)(xr + c);
#pragma unroll
        for (int e = 0; e < E; e++) {
            float4 gv = *(const float4*)(gw + e * H + c);
            acc[e] += xv.x * gv.x + xv.y * gv.y + xv.z * gv.z + xv.w * gv.w;
        }
    }
#pragma unroll
    for (int e = 0; e < E; e++) {
#pragma unroll
        for (int off = 16; off; off >>= 1)
            acc[e] += __shfl_xor_sync(0xffffffffu, acc[e], off);
    }

    if (lane == 0) {
        float m = acc[0];
#pragma unroll
        for (int e = 1; e < E; e++) m = fmaxf(m, acc[e]);
        float p[E], s = 0.f;
#pragma unroll
        for (int e = 0; e < E; e++) { p[e] = expf(acc[e] - m); s += p[e]; }
        float inv = 1.f / s;

        // top-1 (ties -> lowest index, strict >)
        int i0 = 0; float p0 = p[0];
#pragma unroll
        for (int e = 1; e < E; e++) if (p[e] > p0) { p0 = p[e]; i0 = e; }
        // top-2
        int i1 = -1; float p1 = -1.f;
#pragma unroll
        for (int e = 0; e < E; e++) {
            if (e == i0) continue;
            if (p[e] > p1) { p1 = p[e]; i1 = e; }
        }
        p0 *= inv; p1 *= inv;

        int pos0 = atomicAdd(&g_counts[i0], 1);
        g_lists[i0][pos0] = t; g_coefs[i0][pos0] = p0;
        int pos1 = atomicAdd(&g_counts[i1], 1);
        g_lists[i1][pos1] = t; g_coefs[i1][pos1] = p1;
    }
}

__global__ void offsets_kernel() {
    int s = 0;
    for (int e = 0; e < E; e++) { g_offsets[e] = s; s += g_counts[e]; }
}

// ---------------------------------------------------------
// h = silu(x @ w1[e]^T) * (x @ w3[e]^T) over each expert's token list.
// grid: (T/BM, IN/BN, E). 256 threads, each computes 4x4 for BOTH mats.
__global__ __launch_bounds__(256) void gemm13_kernel(
    const float* __restrict__ x,
    const float* __restrict__ w1,
    const float* __restrict__ w3) {
    int e  = blockIdx.z;
    int Me = g_counts[e];
    int m0 = blockIdx.x * BM;
    if (m0 >= Me) return;
    int n0 = blockIdx.y * BN;

    __shared__ float xs[BK][BM];
    __shared__ float b1s[BK][BN];
    __shared__ float b3s[BK][BN];
    __shared__ int   toks[BM];

    int tid = threadIdx.x;
    if (tid < BM) {
        int i = m0 + tid;
        toks[tid] = g_lists[e][i < Me ? i : (Me - 1)];
    }
    __syncthreads();

    float accg[4][4], accu[4][4];
#pragma unroll
    for (int r = 0; r < 4; r++)
#pragma unroll
        for (int c = 0; c < 4; c++) { accg[r][c] = 0.f; accu[r][c] = 0.f; }

    int ty = tid >> 4, tx = tid & 15;
    int li = tid >> 2;            // 0..63 : row within tile
    int lk = (tid & 3) * 4;       // 0,4,8,12 : k offset

    const float* w1e = w1 + (size_t)e * IN * H;
    const float* w3e = w3 + (size_t)e * IN * H;
    const float* xrow = x + (size_t)toks[li] * H + lk;
    const float* w1row = w1e + (size_t)(n0 + li) * H + lk;
    const float* w3row = w3e + (size_t)(n0 + li) * H + lk;

    for (int k0 = 0; k0 < H; k0 += BK) {
        float4 xa = *(const float4*)(xrow + k0);
        float4 wa = *(const float4*)(w1row + k0);
        float4 wb = *(const float4*)(w3row + k0);
        xs[lk + 0][li] = xa.x; xs[lk + 1][li] = xa.y;
        xs[lk + 2][li] = xa.z; xs[lk + 3][li] = xa.w;
        b1s[lk + 0][li] = wa.x; b1s[lk + 1][li] = wa.y;
        b1s[lk + 2][li] = wa.z; b1s[lk + 3][li] = wa.w;
        b3s[lk + 0][li] = wb.x; b3s[lk + 1][li] = wb.y;
        b3s[lk + 2][li] = wb.z; b3s[lk + 3][li] = wb.w;
        __syncthreads();

#pragma unroll
        for (int k = 0; k < BK; k++) {
            float4 av  = *(const float4*)&xs[k][ty * 4];
            float4 b1v = *(const float4*)&b1s[k][tx * 4];
            float4 b3v = *(const float4*)&b3s[k][tx * 4];
            float a[4]  = {av.x,  av.y,  av.z,  av.w};
            float b1[4] = {b1v.x, b1v.y, b1v.z, b1v.w};
            float b3[4] = {b3v.x, b3v.y, b3v.z, b3v.w};
#pragma unroll
            for (int r = 0; r < 4; r++)
#pragma unroll
                for (int c = 0; c < 4; c++) {
                    accg[r][c] += a[r] * b1[c];
                    accu[r][c] += a[r] * b3[c];
                }
        }
        __syncthreads();
    }

    int off = g_offsets[e];
#pragma unroll
    for (int r = 0; r < 4; r++) {
        int i = ty * 4 + r;
        if (m0 + i < Me) {
            float* hp = g_h + ((size_t)(off + m0 + i)) * IN + n0 + tx * 4;
            float4 o;
            float g, u;
            g = accg[r][0]; u = accu[r][0]; o.x = g / (1.f + __expf(-g)) * u;
            g = accg[r][1]; u = accu[r][1]; o.y = g / (1.f + __expf(-g)) * u;
            g = accg[r][2]; u = accu[r][2]; o.z = g / (1.f + __expf(-g)) * u;
            g = accg[r][3]; u = accu[r][3]; o.w = g / (1.f + __expf(-g)) * u;
            *(float4*)hp = o;
        }
    }
}

// ---------------------------------------------------------
// y = h @ w2[e]^T ; out[tok] += coef * y  (atomicAdd; exactly 2 adds/elem)
// grid: (T/BM, H/BN, E)
__global__ __launch_bounds__(256) void gemm2_kernel(
    const float* __restrict__ w2,
    float* __restrict__ out) {
    int e  = blockIdx.z;
    int Me = g_counts[e];
    int m0 = blockIdx.x * BM;
    if (m0 >= Me) return;
    int n0 = blockIdx.y * BN;

    __shared__ float as[BK][BM];
    __shared__ float bs[BK][BN];
    __shared__ int   toks[BM];
    __shared__ float cofs[BM];

    int tid = threadIdx.x;
    if (tid < BM) {
        int i = m0 + tid;
        int ic = i < Me ? i : (Me - 1);
        toks[tid] = g_lists[e][ic];
        cofs[tid] = g_coefs[e][ic];
    }
    __syncthreads();

    float acc[4][4];
#pragma unroll
    for (int r = 0; r < 4; r++)
#pragma unroll
        for (int c = 0; c < 4; c++) acc[r][c] = 0.f;

    int ty = tid >> 4, tx = tid & 15;
    int li = tid >> 2;
    int lk = (tid & 3) * 4;

    int off = g_offsets[e];
    int ri  = m0 + li; if (ri >= Me) ri = Me - 1;
    const float* arow = g_h + ((size_t)(off + ri)) * IN + lk;
    const float* brow = w2 + (size_t)e * H * IN + (size_t)(n0 + li) * IN + lk;

    for (int k0 = 0; k0 < IN; k0 += BK) {
        float4 aa = *(const float4*)(arow + k0);
        float4 bb = *(const float4*)(brow + k0);
        as[lk + 0][li] = aa.x; as[lk + 1][li] = aa.y;
        as[lk + 2][li] = aa.z; as[lk + 3][li] = aa.w;
        bs[lk + 0][li] = bb.x; bs[lk + 1][li] = bb.y;
        bs[lk + 2][li] = bb.z; bs[lk + 3][li] = bb.w;
        __syncthreads();

#pragma unroll
        for (int k = 0; k < BK; k++) {
            float4 av = *(const float4*)&as[k][ty * 4];
            float4 bv = *(const float4*)&bs[k][tx * 4];
            float a[4] = {av.x, av.y, av.z, av.w};
            float b[4] = {bv.x, bv.y, bv.z, bv.w};
#pragma unroll
            for (int r = 0; r < 4; r++)
#pragma unroll
                for (int c = 0; c < 4; c++) acc[r][c] += a[r] * b[c];
        }
        __syncthreads();
    }

#pragma unroll
    for (int r = 0; r < 4; r++) {
        int i = ty * 4 + r;
        if (m0 + i < Me) {
            float coef = cofs[i];
            float* op = out + (size_t)toks[i] * H + n0 + tx * 4;
#pragma unroll
            for (int c = 0; c < 4; c++)
                atomicAdd(op + c, coef * acc[r][c]);
        }
    }
}

// ---------------------------------------------------------
extern "C" void kernel_launch(void* const* d_in, const int* in_sizes, int n_in,
                              void* d_out, int out_size) {
    const float* x  = (const float*)d_in[0];
    const float* gw = (const float*)d_in[1];
    const float* w1 = (const float*)d_in[2];
    const float* w2 = (const float*)d_in[3];
    const float* w3 = (const float*)d_in[4];
    float* out = (float*)d_out;

    cudaMemsetAsync(d_out, 0, (size_t)T * H * sizeof(float));
    zero_counts_kernel<<<1, 32>>>();
    router_kernel<<<T / 8, 256>>>(x, gw);
    offsets_kernel<<<1, 1>>>();
    gemm13_kernel<<<dim3(T / BM, IN / BN, E), 256>>>(x, w1, w3);
    gemm2_kernel<<<dim3(T / BM, H / BN, E), 256>>>(w2, out);
}

// round 6
// speedup vs baseline: 2.7638x; 2.7638x over previous
#include <cuda_runtime.h>
#include <cuda_bf16.h>
#include <cstdint>
#include <math.h>

#define T 8192
#define H 2048
#define IN 4096
#define E 8

#define WS 12            // padded words per 16-k row (8 data + 4 pad)
#define PLANE (128 * WS) // words per 128-row plane

// ---- scratch ----
__device__ int      g_counts[E];
__device__ int      g_offsets[E];
__device__ int      g_lists[E][T];
__device__ float    g_coefs[E][T];
__device__ uint32_t g_h_hi[(size_t)2 * T * (IN / 2)]; // h as bf16x2 words, hi plane
__device__ uint32_t g_h_lo[(size_t)2 * T * (IN / 2)]; // lo (residual) plane

// f32 pair -> bf16x2 hi + bf16x2 residual lo  (elem k in LOW half)
__device__ __forceinline__ void split2(float f0, float f1, uint32_t& hi, uint32_t& lo) {
    asm("cvt.rn.bf16x2.f32 %0, %1, %2;" : "=r"(hi) : "f"(f1), "f"(f0));
    float h0 = __uint_as_float(hi << 16);
    float h1 = __uint_as_float(hi & 0xffff0000u);
    asm("cvt.rn.bf16x2.f32 %0, %1, %2;" : "=r"(lo) : "f"(f1 - h1), "f"(f0 - h0));
}
__device__ __forceinline__ void pack8(const float4& v0, const float4& v1, uint4& hi, uint4& lo) {
    split2(v0.x, v0.y, hi.x, lo.x);
    split2(v0.z, v0.w, hi.y, lo.y);
    split2(v1.x, v1.y, hi.z, lo.z);
    split2(v1.z, v1.w, hi.w, lo.w);
}
__device__ __forceinline__ void mma_bf16(float c[4], const uint32_t a[4], uint32_t b0, uint32_t b1) {
    asm volatile("mma.sync.aligned.m16n8k16.row.col.f32.bf16.bf16.f32 "
                 "{%0,%1,%2,%3}, {%4,%5,%6,%7}, {%8,%9}, {%0,%1,%2,%3};"
                 : "+f"(c[0]), "+f"(c[1]), "+f"(c[2]), "+f"(c[3])
                 : "r"(a[0]), "r"(a[1]), "r"(a[2]), "r"(a[3]), "r"(b0), "r"(b1));
}

// ================= router =================
__global__ void zero_counts_kernel() { if (threadIdx.x < E) g_counts[threadIdx.x] = 0; }

__global__ void router_kernel(const float* __restrict__ x, const float* __restrict__ gw) {
    int t = blockIdx.x * (blockDim.x >> 5) + (threadIdx.x >> 5);
    int lane = threadIdx.x & 31;
    if (t >= T) return;
    float acc[E];
#pragma unroll
    for (int e = 0; e < E; e++) acc[e] = 0.f;
    const float* xr = x + (size_t)t * H;
    for (int c = lane * 4; c < H; c += 128) {
        float4 xv = *(const float4*)(xr + c);
#pragma unroll
        for (int e = 0; e < E; e++) {
            float4 gv = *(const float4*)(gw + e * H + c);
            acc[e] += xv.x * gv.x + xv.y * gv.y + xv.z * gv.z + xv.w * gv.w;
        }
    }
#pragma unroll
    for (int e = 0; e < E; e++)
#pragma unroll
        for (int o = 16; o; o >>= 1) acc[e] += __shfl_xor_sync(0xffffffffu, acc[e], o);
    if (lane == 0) {
        float m = acc[0];
#pragma unroll
        for (int e = 1; e < E; e++) m = fmaxf(m, acc[e]);
        float p[E], s = 0.f;
#pragma unroll
        for (int e = 0; e < E; e++) { p[e] = expf(acc[e] - m); s += p[e]; }
        float inv = 1.f / s;
        int i0 = 0; float p0 = p[0];
#pragma unroll
        for (int e = 1; e < E; e++) if (p[e] > p0) { p0 = p[e]; i0 = e; }
        int i1 = -1; float p1 = -1.f;
#pragma unroll
        for (int e = 0; e < E; e++) { if (e == i0) continue; if (p[e] > p1) { p1 = p[e]; i1 = e; } }
        p0 *= inv; p1 *= inv;
        int q0 = atomicAdd(&g_counts[i0], 1); g_lists[i0][q0] = t; g_coefs[i0][q0] = p0;
        int q1 = atomicAdd(&g_counts[i1], 1); g_lists[i1][q1] = t; g_coefs[i1][q1] = p1;
    }
}

__global__ void offsets_kernel() {
    int s = 0;
    for (int e = 0; e < E; e++) { g_offsets[e] = s; s += g_counts[e]; }
}

// ================= gemm13: h = silu(x@w1^T) * (x@w3^T) =================
// 128x128 tile, 8 warps (2x4), warp tile 64x32, bf16x3 via mma.sync m16n8k16.
// SMEM words: toks[128] + 2 stages x 6 planes (Ah,Al,B1h,B1l,B3h,B3l).
#define SM13_BYTES ((128 + 2 * 6 * PLANE) * 4)

__global__ void __launch_bounds__(256, 1) gemm13_kernel(
    const float* __restrict__ x, const float* __restrict__ w1, const float* __restrict__ w3) {
    int e = blockIdx.z, Me = g_counts[e], m0 = blockIdx.x * 128;
    if (m0 >= Me) return;
    int n0 = blockIdx.y * 128;

    extern __shared__ uint32_t smw[];
    int* toks = (int*)smw;
    uint32_t* planes = smw + 128;

    int tid = threadIdx.x, wid = tid >> 5, lane = tid & 31;
    if (tid < 128) { int i = m0 + tid; toks[tid] = g_lists[e][i < Me ? i : (Me - 1)]; }
    __syncthreads();

    int r = tid >> 1, hf = tid & 1;                   // loader: row, k-half (8 fp32)
    const float* xr  = x  + (size_t)toks[r] * H + hf * 8;
    const float* w1r = w1 + ((size_t)e * IN + n0 + r) * H + hf * 8;
    const float* w3r = w3 + ((size_t)e * IN + n0 + r) * H + hf * 8;
    int sidx = r * WS + hf * 4;

    int wm = wid & 1, wn = wid >> 1;                  // warp tile origin
    int r0 = lane >> 2, c0 = lane & 3;

    float accg[4][4][4], accu[4][4][4];
#pragma unroll
    for (int mi = 0; mi < 4; mi++)
#pragma unroll
        for (int ni = 0; ni < 4; ni++)
#pragma unroll
            for (int q = 0; q < 4; q++) { accg[mi][ni][q] = 0.f; accu[mi][ni][q] = 0.f; }

    float4 pa0, pa1, pb0, pb1, pc0, pc1;
    // prologue: stage 0
    pa0 = *(const float4*)(xr);      pa1 = *(const float4*)(xr + 4);
    pb0 = *(const float4*)(w1r);     pb1 = *(const float4*)(w1r + 4);
    pc0 = *(const float4*)(w3r);     pc1 = *(const float4*)(w3r + 4);
    {
        uint4 hv, lv;
        pack8(pa0, pa1, hv, lv);
        *(uint4*)(planes + 0 * PLANE + sidx) = hv; *(uint4*)(planes + 1 * PLANE + sidx) = lv;
        pack8(pb0, pb1, hv, lv);
        *(uint4*)(planes + 2 * PLANE + sidx) = hv; *(uint4*)(planes + 3 * PLANE + sidx) = lv;
        pack8(pc0, pc1, hv, lv);
        *(uint4*)(planes + 4 * PLANE + sidx) = hv; *(uint4*)(planes + 5 * PLANE + sidx) = lv;
    }
    __syncthreads();

    const int NIT = H / 16;   // 128
#pragma unroll 1
    for (int it = 0; it < NIT; it++) {
        int s = it & 1;
        if (it + 1 < NIT) {
            int k0 = (it + 1) * 16;
            pa0 = *(const float4*)(xr + k0);  pa1 = *(const float4*)(xr + k0 + 4);
            pb0 = *(const float4*)(w1r + k0); pb1 = *(const float4*)(w1r + k0 + 4);
            pc0 = *(const float4*)(w3r + k0); pc1 = *(const float4*)(w3r + k0 + 4);
        }
        const uint32_t* st = planes + s * 6 * PLANE;
        uint32_t ah[4][4], al[4][4];
#pragma unroll
        for (int mi = 0; mi < 4; mi++) {
            int base = (wm * 64 + mi * 16 + r0) * WS + c0;
            ah[mi][0] = st[base];           ah[mi][1] = st[base + 8 * WS];
            ah[mi][2] = st[base + 4];       ah[mi][3] = st[base + 8 * WS + 4];
            const uint32_t* stl = st + PLANE;
            al[mi][0] = stl[base];          al[mi][1] = stl[base + 8 * WS];
            al[mi][2] = stl[base + 4];      al[mi][3] = stl[base + 8 * WS + 4];
        }
#pragma unroll
        for (int ni = 0; ni < 4; ni++) {
            int bb = (wn * 32 + ni * 8 + r0) * WS + c0;
            uint32_t b1h0 = st[2 * PLANE + bb], b1h1 = st[2 * PLANE + bb + 4];
            uint32_t b1l0 = st[3 * PLANE + bb], b1l1 = st[3 * PLANE + bb + 4];
            uint32_t b3h0 = st[4 * PLANE + bb], b3h1 = st[4 * PLANE + bb + 4];
            uint32_t b3l0 = st[5 * PLANE + bb], b3l1 = st[5 * PLANE + bb + 4];
#pragma unroll
            for (int mi = 0; mi < 4; mi++) {
                mma_bf16(accg[mi][ni], ah[mi], b1h0, b1h1);
                mma_bf16(accg[mi][ni], ah[mi], b1l0, b1l1);
                mma_bf16(accg[mi][ni], al[mi], b1h0, b1h1);
                mma_bf16(accu[mi][ni], ah[mi], b3h0, b3h1);
                mma_bf16(accu[mi][ni], ah[mi], b3l0, b3l1);
                mma_bf16(accu[mi][ni], al[mi], b3h0, b3h1);
            }
        }
        if (it + 1 < NIT) {
            uint32_t* dt = planes + (s ^ 1) * 6 * PLANE;
            uint4 hv, lv;
            pack8(pa0, pa1, hv, lv);
            *(uint4*)(dt + 0 * PLANE + sidx) = hv; *(uint4*)(dt + 1 * PLANE + sidx) = lv;
            pack8(pb0, pb1, hv, lv);
            *(uint4*)(dt + 2 * PLANE + sidx) = hv; *(uint4*)(dt + 3 * PLANE + sidx) = lv;
            pack8(pc0, pc1, hv, lv);
            *(uint4*)(dt + 4 * PLANE + sidx) = hv; *(uint4*)(dt + 5 * PLANE + sidx) = lv;
        }
        __syncthreads();
    }

    // epilogue: h = silu(g)*u -> bf16 hi/lo words, direct global store
    int off = g_offsets[e];
#pragma unroll
    for (int mi = 0; mi < 4; mi++)
#pragma unroll
        for (int ni = 0; ni < 4; ni++) {
            int row = wm * 64 + mi * 16 + r0;
            int col = wn * 32 + ni * 8 + c0 * 2;
            const float* cg = accg[mi][ni];
            const float* cu = accu[mi][ni];
#pragma unroll
            for (int half = 0; half < 2; half++) {
                int rr = row + half * 8;
                if (m0 + rr < Me) {
                    float g0 = cg[half * 2], g1 = cg[half * 2 + 1];
                    float u0 = cu[half * 2], u1 = cu[half * 2 + 1];
                    float h0 = g0 / (1.f + __expf(-g0)) * u0;
                    float h1 = g1 / (1.f + __expf(-g1)) * u1;
                    uint32_t hv, lv;
                    split2(h0, h1, hv, lv);
                    size_t p = (size_t)(off + m0 + rr) * (IN / 2) + ((n0 + col) >> 1);
                    g_h_hi[p] = hv;
                    g_h_lo[p] = lv;
                }
            }
        }
}

// ================= gemm2: out[tok] += coef * (h @ w2^T) =================
#define SM2_BYTES ((256 + 2 * 4 * PLANE) * 4)

__global__ void __launch_bounds__(256, 1) gemm2_kernel(
    const float* __restrict__ w2, float* __restrict__ out) {
    int e = blockIdx.z, Me = g_counts[e], m0 = blockIdx.x * 128;
    if (m0 >= Me) return;
    int n0 = blockIdx.y * 128;

    extern __shared__ uint32_t smw[];
    int*   toks = (int*)smw;
    float* cofs = (float*)(smw + 128);
    uint32_t* planes = smw + 256;

    int tid = threadIdx.x, wid = tid >> 5, lane = tid & 31;
    if (tid < 128) {
        int i = m0 + tid, ic = i < Me ? i : (Me - 1);
        toks[tid] = g_lists[e][ic];
        cofs[tid] = g_coefs[e][ic];
    }
    __syncthreads();

    int r = tid >> 1, hf = tid & 1;
    int off = g_offsets[e];
    int ri = m0 + r; if (ri >= Me) ri = Me - 1;
    const uint32_t* hhr = g_h_hi + (size_t)(off + ri) * (IN / 2) + hf * 4;
    const uint32_t* hlr = g_h_lo + (size_t)(off + ri) * (IN / 2) + hf * 4;
    const float*    w2r = w2 + ((size_t)e * H + n0 + r) * IN + hf * 8;
    int sidx = r * WS + hf * 4;

    int wm = wid & 1, wn = wid >> 1;
    int r0 = lane >> 2, c0 = lane & 3;

    float acc[4][4][4];
#pragma unroll
    for (int mi = 0; mi < 4; mi++)
#pragma unroll
        for (int ni = 0; ni < 4; ni++)
#pragma unroll
            for (int q = 0; q < 4; q++) acc[mi][ni][q] = 0.f;

    uint4 pha, pla;
    float4 pb0, pb1;
    pha = *(const uint4*)(hhr); pla = *(const uint4*)(hlr);
    pb0 = *(const float4*)(w2r); pb1 = *(const float4*)(w2r + 4);
    {
        *(uint4*)(planes + 0 * PLANE + sidx) = pha;
        *(uint4*)(planes + 1 * PLANE + sidx) = pla;
        uint4 hv, lv;
        pack8(pb0, pb1, hv, lv);
        *(uint4*)(planes + 2 * PLANE + sidx) = hv;
        *(uint4*)(planes + 3 * PLANE + sidx) = lv;
    }
    __syncthreads();

    const int NIT = IN / 16;  // 256
#pragma unroll 1
    for (int it = 0; it < NIT; it++) {
        int s = it & 1;
        if (it + 1 < NIT) {
            int kw = (it + 1) * 8, k0 = (it + 1) * 16;
            pha = *(const uint4*)(hhr + kw); pla = *(const uint4*)(hlr + kw);
            pb0 = *(const float4*)(w2r + k0); pb1 = *(const float4*)(w2r + k0 + 4);
        }
        const uint32_t* st = planes + s * 4 * PLANE;
        uint32_t ah[4][4], al[4][4];
#pragma unroll
        for (int mi = 0; mi < 4; mi++) {
            int base = (wm * 64 + mi * 16 + r0) * WS + c0;
            ah[mi][0] = st[base];       ah[mi][1] = st[base + 8 * WS];
            ah[mi][2] = st[base + 4];   ah[mi][3] = st[base + 8 * WS + 4];
            const uint32_t* stl = st + PLANE;
            al[mi][0] = stl[base];      al[mi][1] = stl[base + 8 * WS];
            al[mi][2] = stl[base + 4];  al[mi][3] = stl[base + 8 * WS + 4];
        }
#pragma unroll
        for (int ni = 0; ni < 4; ni++) {
            int bb = (wn * 32 + ni * 8 + r0) * WS + c0;
            uint32_t bh0 = st[2 * PLANE + bb], bh1 = st[2 * PLANE + bb + 4];
            uint32_t bl0 = st[3 * PLANE + bb], bl1 = st[3 * PLANE + bb + 4];
#pragma unroll
            for (int mi = 0; mi < 4; mi++) {
                mma_bf16(acc[mi][ni], ah[mi], bh0, bh1);
                mma_bf16(acc[mi][ni], ah[mi], bl0, bl1);
                mma_bf16(acc[mi][ni], al[mi], bh0, bh1);
            }
        }
        if (it + 1 < NIT) {
            uint32_t* dt = planes + (s ^ 1) * 4 * PLANE;
            *(uint4*)(dt + 0 * PLANE + sidx) = pha;
            *(uint4*)(dt + 1 * PLANE + sidx) = pla;
            uint4 hv, lv;
            pack8(pb0, pb1, hv, lv);
            *(uint4*)(dt + 2 * PLANE + sidx) = hv;
            *(uint4*)(dt + 3 * PLANE + sidx) = lv;
        }
        __syncthreads();
    }

    // epilogue: scale by coef, atomicAdd into out
#pragma unroll
    for (int mi = 0; mi < 4; mi++)
#pragma unroll
        for (int ni = 0; ni < 4; ni++) {
            int row = wm * 64 + mi * 16 + r0;
            int col = wn * 32 + ni * 8 + c0 * 2;
            const float* c = acc[mi][ni];
#pragma unroll
            for (int half = 0; half < 2; half++) {
                int rr = row + half * 8;
                if (m0 + rr < Me) {
                    float cf = cofs[rr];
                    float* op = out + (size_t)toks[rr] * H + n0 + col;
                    atomicAdd(op,     cf * c[half * 2]);
                    atomicAdd(op + 1, cf * c[half * 2 + 1]);
                }
            }
        }
}

// ================= launch =================
extern "C" void kernel_launch(void* const* d_in, const int* in_sizes, int n_in,
                              void* d_out, int out_size) {
    const float* x  = (const float*)d_in[0];
    const float* gw = (const float*)d_in[1];
    const float* w1 = (const float*)d_in[2];
    const float* w2 = (const float*)d_in[3];
    const float* w3 = (const float*)d_in[4];
    float* out = (float*)d_out;

    cudaFuncSetAttribute(gemm13_kernel, cudaFuncAttributeMaxDynamicSharedMemorySize, SM13_BYTES);
    cudaFuncSetAttribute(gemm2_kernel,  cudaFuncAttributeMaxDynamicSharedMemorySize, SM2_BYTES);

    cudaMemsetAsync(d_out, 0, (size_t)T * H * sizeof(float));
    zero_counts_kernel<<<1, 32>>>();
    router_kernel<<<T / 8, 256>>>(x, gw);
    offsets_kernel<<<1, 1>>>();
    gemm13_kernel<<<dim3(T / 128, IN / 128, E), 256, SM13_BYTES>>>(x, w1, w3);
    gemm2_kernel<<<dim3(T / 128, H / 128, E), 256, SM2_BYTES>>>(w2, out);
}